// round 1
// baseline (speedup 1.0000x reference)
#include <cuda_runtime.h>
#include <cstdint>

#define NROWS 200000
#define CIN1  64
#define COUT  128
#define NTAPS 27
#define EPSBN 1e-5f
#define STATS_BLOCKS 256

// ---------------- scratch (device globals; no allocation allowed) ----------
__device__ float g_hpre[(size_t)NROWS * COUT];    // conv1 pre-BN, then BN'd in place
__device__ float g_respre[(size_t)NROWS * COUT];  // conv2 pre-BN
__device__ float g_skippre[(size_t)NROWS * COUT]; // skip pre-BN
__device__ float g_part_sum[STATS_BLOCKS][COUT];
__device__ float g_part_sq[STATS_BLOCKS][COUT];
__device__ float g_inv[3][COUT];    // g * rsqrt(var+eps)
__device__ float g_shift[3][COUT];  // b - mean*inv

// ---------------- packed f32x2 helpers -------------------------------------
__device__ __forceinline__ unsigned long long pack2(float lo, float hi) {
    unsigned long long r;
    asm("mov.b64 %0, {%1,%2};" : "=l"(r) : "f"(lo), "f"(hi));
    return r;
}
__device__ __forceinline__ unsigned long long fma2(unsigned long long a,
                                                   unsigned long long b,
                                                   unsigned long long c) {
    unsigned long long d;
    asm("fma.rn.f32x2 %0, %1, %2, %3;" : "=l"(d) : "l"(a), "l"(b), "l"(c));
    return d;
}
__device__ __forceinline__ float2 unpack2(unsigned long long v) {
    float2 f;
    asm("mov.b64 {%0,%1}, %2;" : "=f"(f.x), "=f"(f.y) : "l"(v));
    return f;
}

// ---------------- gathered multi-tap GEMM -----------------------------------
// Y[i, :] = sum_k X[nbr[k,i], :] @ W[k]   (idx==NROWS sentinel -> zero row)
// Tile: 128 rows x 128 cols per CTA, 256 threads, 8x8 per thread (f32x2 accs).
template <int CIN_T, bool GATHER>
__global__ __launch_bounds__(256, 2)
void conv_kernel(const float* __restrict__ X, const int* __restrict__ nbr,
                 const float* __restrict__ W, float* __restrict__ Y, int ntaps) {
    constexpr int BM = 128, BN = 128, CK = 32;
    __shared__ float Xs[BM][CK];   // gathered input tile (2-way LDS conflict accepted)
    __shared__ float Ws[CK][BN];

    const int tid = threadIdx.x;
    const int rg = tid >> 4;   // 0..15 : row group (8 rows each)
    const int cg = tid & 15;   // 0..15 : col group (8 cols each)
    const int row0 = blockIdx.x * BM;

    unsigned long long acc[8][4];
#pragma unroll
    for (int i = 0; i < 8; i++)
#pragma unroll
        for (int j = 0; j < 4; j++) acc[i][j] = 0ull;

    for (int k = 0; k < ntaps; k++) {
        const float* Wk = W + (size_t)k * CIN_T * BN;
#pragma unroll
        for (int c0 = 0; c0 < CIN_T; c0 += CK) {
            // ---- load gathered X tile: 128 rows x 32 floats (float4 granularity)
#pragma unroll
            for (int it = 0; it < (BM * CK / 4) / 256; it++) {
                int id = tid + it * 256;     // 0..1023
                int r  = id >> 3;            // 8 float4 per row
                int c4 = id & 7;
                int grow = row0 + r;
                int src;
                if (GATHER)
                    src = (grow < NROWS) ? nbr[(size_t)k * NROWS + grow] : NROWS;
                else
                    src = grow;
                float4 v = make_float4(0.f, 0.f, 0.f, 0.f);
                if ((unsigned)src < (unsigned)NROWS)
                    v = *(const float4*)(X + (size_t)src * CIN_T + c0 + c4 * 4);
                *(float4*)(&Xs[r][c4 * 4]) = v;
            }
            // ---- load W chunk: 32 x 128
#pragma unroll
            for (int it = 0; it < (CK * BN / 4) / 256; it++) {
                int id = tid + it * 256;     // 0..1023
                int r  = id >> 5;            // 32 float4 per row
                int c4 = id & 31;
                float4 v = *(const float4*)(Wk + (size_t)(c0 + r) * BN + c4 * 4);
                *(float4*)(&Ws[r][c4 * 4]) = v;
            }
            __syncthreads();

            // ---- compute: per cc, 8 broadcast x, 8 w (2 float4), 32 FFMA2
#pragma unroll
            for (int cc = 0; cc < CK; cc++) {
                unsigned long long x2[8];
#pragma unroll
                for (int i = 0; i < 8; i++) {
                    float xv = Xs[rg * 8 + i][cc];
                    x2[i] = pack2(xv, xv);
                }
                const float4* wrow = (const float4*)(&Ws[cc][cg * 8]);
                float4 wa = wrow[0], wb = wrow[1];
                unsigned long long w0 = pack2(wa.x, wa.y);
                unsigned long long w1 = pack2(wa.z, wa.w);
                unsigned long long w2 = pack2(wb.x, wb.y);
                unsigned long long w3 = pack2(wb.z, wb.w);
#pragma unroll
                for (int i = 0; i < 8; i++) {
                    acc[i][0] = fma2(x2[i], w0, acc[i][0]);
                    acc[i][1] = fma2(x2[i], w1, acc[i][1]);
                    acc[i][2] = fma2(x2[i], w2, acc[i][2]);
                    acc[i][3] = fma2(x2[i], w3, acc[i][3]);
                }
            }
            __syncthreads();
        }
    }

    // ---- store
    const int gcol = cg * 8;
#pragma unroll
    for (int i = 0; i < 8; i++) {
        int grow = row0 + rg * 8 + i;
        if (grow < NROWS) {
            float2 p0 = unpack2(acc[i][0]);
            float2 p1 = unpack2(acc[i][1]);
            float2 p2 = unpack2(acc[i][2]);
            float2 p3 = unpack2(acc[i][3]);
            float4* yp = (float4*)(Y + (size_t)grow * BN + gcol);
            yp[0] = make_float4(p0.x, p0.y, p1.x, p1.y);
            yp[1] = make_float4(p2.x, p2.y, p3.x, p3.y);
        }
    }
}

// ---------------- deterministic column stats --------------------------------
__global__ void stats_kernel(const float* __restrict__ X) {
    __shared__ float ssum[2][COUT];
    __shared__ float ssq[2][COUT];
    const int col = threadIdx.x & (COUT - 1);
    const int half = threadIdx.x >> 7;
    float s = 0.f, q = 0.f;
    for (long long r = (long long)blockIdx.x * 2 + half; r < NROWS;
         r += (long long)gridDim.x * 2) {
        float v = X[r * COUT + col];
        s += v;
        q += v * v;
    }
    ssum[half][col] = s;
    ssq[half][col] = q;
    __syncthreads();
    if (half == 0) {
        g_part_sum[blockIdx.x][col] = ssum[0][col] + ssum[1][col];
        g_part_sq[blockIdx.x][col]  = ssq[0][col] + ssq[1][col];
    }
}

__global__ void finalize_kernel(const float* __restrict__ g,
                                const float* __restrict__ b, int slot) {
    const int col = threadIdx.x;  // 128 threads
    float s = 0.f, q = 0.f;
    for (int i = 0; i < STATS_BLOCKS; i++) {
        s += g_part_sum[i][col];
        q += g_part_sq[i][col];
    }
    float mean = s * (1.0f / NROWS);
    float var = q * (1.0f / NROWS) - mean * mean;
    float inv = g[col] * rsqrtf(var + EPSBN);
    g_inv[slot][col] = inv;
    g_shift[slot][col] = b[col] - mean * inv;
}

// ---------------- BN apply (in place, slot 0) --------------------------------
__global__ void bn_apply_kernel(float4* __restrict__ X) {
    long long i = (long long)blockIdx.x * blockDim.x + threadIdx.x;
    const long long total = (long long)NROWS * COUT / 4;
    if (i >= total) return;
    int c4 = (int)(i & (COUT / 4 - 1)) * 4;
    float4 v = X[i];
    v.x = v.x * g_inv[0][c4 + 0] + g_shift[0][c4 + 0];
    v.y = v.y * g_inv[0][c4 + 1] + g_shift[0][c4 + 1];
    v.z = v.z * g_inv[0][c4 + 2] + g_shift[0][c4 + 2];
    v.w = v.w * g_inv[0][c4 + 3] + g_shift[0][c4 + 3];
    X[i] = v;
}

// ---------------- final: relu(bn(res) + bn(skip)) ----------------------------
__global__ void final_kernel(float4* __restrict__ out) {
    long long i = (long long)blockIdx.x * blockDim.x + threadIdx.x;
    const long long total = (long long)NROWS * COUT / 4;
    if (i >= total) return;
    int c4 = (int)(i & (COUT / 4 - 1)) * 4;
    const float4 r = ((const float4*)g_respre)[i];
    const float4 s = ((const float4*)g_skippre)[i];
    float4 o;
    o.x = fmaxf(r.x * g_inv[1][c4 + 0] + g_shift[1][c4 + 0] +
                s.x * g_inv[2][c4 + 0] + g_shift[2][c4 + 0], 0.f);
    o.y = fmaxf(r.y * g_inv[1][c4 + 1] + g_shift[1][c4 + 1] +
                s.y * g_inv[2][c4 + 1] + g_shift[2][c4 + 1], 0.f);
    o.z = fmaxf(r.z * g_inv[1][c4 + 2] + g_shift[1][c4 + 2] +
                s.z * g_inv[2][c4 + 2] + g_shift[2][c4 + 2], 0.f);
    o.w = fmaxf(r.w * g_inv[1][c4 + 3] + g_shift[1][c4 + 3] +
                s.w * g_inv[2][c4 + 3] + g_shift[2][c4 + 3], 0.f);
    out[i] = o;
}

// ---------------- launch ------------------------------------------------------
extern "C" void kernel_launch(void* const* d_in, const int* in_sizes, int n_in,
                              void* d_out, int out_size) {
    const float* feats = (const float*)d_in[0];
    const int*   nbr   = (const int*)d_in[1];
    const float* W1    = (const float*)d_in[2];
    const float* g1    = (const float*)d_in[3];
    const float* b1    = (const float*)d_in[4];
    const float* W2    = (const float*)d_in[5];
    const float* g2    = (const float*)d_in[6];
    const float* b2    = (const float*)d_in[7];
    const float* Wsk   = (const float*)d_in[8];
    const float* gsk   = (const float*)d_in[9];
    const float* bsk   = (const float*)d_in[10];
    float* out = (float*)d_out;

    float *hpre, *respre, *skippre;
    cudaGetSymbolAddress((void**)&hpre, g_hpre);
    cudaGetSymbolAddress((void**)&respre, g_respre);
    cudaGetSymbolAddress((void**)&skippre, g_skippre);

    const int grid = (NROWS + 127) / 128;  // 1563
    const long long total4 = (long long)NROWS * COUT / 4;
    const int egrid = (int)((total4 + 255) / 256);

    // skip branch pre-BN: feats @ Wsk
    conv_kernel<CIN1, false><<<grid, 256>>>(feats, nullptr, Wsk, skippre, 1);
    // conv1 pre-BN
    conv_kernel<CIN1, true><<<grid, 256>>>(feats, nbr, W1, hpre, NTAPS);
    // BN1 stats + apply in place
    stats_kernel<<<STATS_BLOCKS, 256>>>(hpre);
    finalize_kernel<<<1, COUT>>>(g1, b1, 0);
    bn_apply_kernel<<<egrid, 256>>>((float4*)hpre);
    // conv2 pre-BN
    conv_kernel<COUT, true><<<grid, 256>>>(hpre, nbr, W2, respre, NTAPS);
    // BN2 + BNskip stats
    stats_kernel<<<STATS_BLOCKS, 256>>>(respre);
    finalize_kernel<<<1, COUT>>>(g2, b2, 1);
    stats_kernel<<<STATS_BLOCKS, 256>>>(skippre);
    finalize_kernel<<<1, COUT>>>(gsk, bsk, 2);
    // out = relu(bn(res) + bn(skip))
    final_kernel<<<egrid, 256>>>((float4*)out);
}

// round 2
// speedup vs baseline: 1.0052x; 1.0052x over previous
#include <cuda_runtime.h>
#include <cstdint>

#define NROWS 200000
#define CIN1  64
#define COUT  128
#define NTAPS 27
#define EPSBN 1e-5f
#define STATS_BLOCKS 256

// ---------------- scratch (device globals; no allocation allowed) ----------
__device__ float g_hpre[(size_t)NROWS * COUT];    // conv1 pre-BN, then BN'd in place
__device__ float g_respre[(size_t)NROWS * COUT];  // conv2 pre-BN
__device__ float g_skippre[(size_t)NROWS * COUT]; // skip pre-BN
__device__ float g_part_sum[STATS_BLOCKS][COUT];
__device__ float g_part_sq[STATS_BLOCKS][COUT];
__device__ float g_inv[3][COUT];    // g * rsqrt(var+eps)
__device__ float g_shift[3][COUT];  // b - mean*inv

// ---------------- packed f32x2 helpers -------------------------------------
__device__ __forceinline__ unsigned long long pack2(float lo, float hi) {
    unsigned long long r;
    asm("mov.b64 %0, {%1,%2};" : "=l"(r) : "f"(lo), "f"(hi));
    return r;
}
__device__ __forceinline__ unsigned long long fma2(unsigned long long a,
                                                   unsigned long long b,
                                                   unsigned long long c) {
    unsigned long long d;
    asm("fma.rn.f32x2 %0, %1, %2, %3;" : "=l"(d) : "l"(a), "l"(b), "l"(c));
    return d;
}
__device__ __forceinline__ float2 unpack2(unsigned long long v) {
    float2 f;
    asm("mov.b64 {%0,%1}, %2;" : "=f"(f.x), "=f"(f.y) : "l"(v));
    return f;
}

// ---------------- gathered multi-tap GEMM -----------------------------------
// Y[i, :] = sum_k X[nbr[k,i], :] @ W[k]   (idx==NROWS sentinel -> zero row)
// Tile: 128 rows x 128 cols per CTA, 256 threads, 8x8 per thread (f32x2 accs).
template <int CIN_T, bool GATHER>
__global__ __launch_bounds__(256, 2)
void conv_kernel(const float* __restrict__ X, const int* __restrict__ nbr,
                 const float* __restrict__ W, float* __restrict__ Y, int ntaps) {
    constexpr int BM = 128, BN = 128, CK = 32;
    __shared__ float Xs[BM][CK];   // gathered input tile (2-way LDS conflict accepted)
    __shared__ float Ws[CK][BN];

    const int tid = threadIdx.x;
    const int rg = tid >> 4;   // 0..15 : row group (8 rows each)
    const int cg = tid & 15;   // 0..15 : col group (8 cols each)
    const int row0 = blockIdx.x * BM;

    unsigned long long acc[8][4];
#pragma unroll
    for (int i = 0; i < 8; i++)
#pragma unroll
        for (int j = 0; j < 4; j++) acc[i][j] = 0ull;

    for (int k = 0; k < ntaps; k++) {
        const float* Wk = W + (size_t)k * CIN_T * BN;
#pragma unroll
        for (int c0 = 0; c0 < CIN_T; c0 += CK) {
            // ---- load gathered X tile: 128 rows x 32 floats (float4 granularity)
#pragma unroll
            for (int it = 0; it < (BM * CK / 4) / 256; it++) {
                int id = tid + it * 256;     // 0..1023
                int r  = id >> 3;            // 8 float4 per row
                int c4 = id & 7;
                int grow = row0 + r;
                int src;
                if (GATHER)
                    src = (grow < NROWS) ? nbr[(size_t)k * NROWS + grow] : NROWS;
                else
                    src = grow;
                float4 v = make_float4(0.f, 0.f, 0.f, 0.f);
                if ((unsigned)src < (unsigned)NROWS)
                    v = *(const float4*)(X + (size_t)src * CIN_T + c0 + c4 * 4);
                *(float4*)(&Xs[r][c4 * 4]) = v;
            }
            // ---- load W chunk: 32 x 128
#pragma unroll
            for (int it = 0; it < (CK * BN / 4) / 256; it++) {
                int id = tid + it * 256;     // 0..1023
                int r  = id >> 5;            // 32 float4 per row
                int c4 = id & 31;
                float4 v = *(const float4*)(Wk + (size_t)(c0 + r) * BN + c4 * 4);
                *(float4*)(&Ws[r][c4 * 4]) = v;
            }
            __syncthreads();

            // ---- compute: per cc, 8 broadcast x, 8 w (2 float4), 32 FFMA2
#pragma unroll
            for (int cc = 0; cc < CK; cc++) {
                unsigned long long x2[8];
#pragma unroll
                for (int i = 0; i < 8; i++) {
                    float xv = Xs[rg * 8 + i][cc];
                    x2[i] = pack2(xv, xv);
                }
                const float4* wrow = (const float4*)(&Ws[cc][cg * 8]);
                float4 wa = wrow[0], wb = wrow[1];
                unsigned long long w0 = pack2(wa.x, wa.y);
                unsigned long long w1 = pack2(wa.z, wa.w);
                unsigned long long w2 = pack2(wb.x, wb.y);
                unsigned long long w3 = pack2(wb.z, wb.w);
#pragma unroll
                for (int i = 0; i < 8; i++) {
                    acc[i][0] = fma2(x2[i], w0, acc[i][0]);
                    acc[i][1] = fma2(x2[i], w1, acc[i][1]);
                    acc[i][2] = fma2(x2[i], w2, acc[i][2]);
                    acc[i][3] = fma2(x2[i], w3, acc[i][3]);
                }
            }
            __syncthreads();
        }
    }

    // ---- store
    const int gcol = cg * 8;
#pragma unroll
    for (int i = 0; i < 8; i++) {
        int grow = row0 + rg * 8 + i;
        if (grow < NROWS) {
            float2 p0 = unpack2(acc[i][0]);
            float2 p1 = unpack2(acc[i][1]);
            float2 p2 = unpack2(acc[i][2]);
            float2 p3 = unpack2(acc[i][3]);
            float4* yp = (float4*)(Y + (size_t)grow * BN + gcol);
            yp[0] = make_float4(p0.x, p0.y, p1.x, p1.y);
            yp[1] = make_float4(p2.x, p2.y, p3.x, p3.y);
        }
    }
}

// ---------------- deterministic column stats --------------------------------
__global__ void stats_kernel(const float* __restrict__ X) {
    __shared__ float ssum[2][COUT];
    __shared__ float ssq[2][COUT];
    const int col = threadIdx.x & (COUT - 1);
    const int half = threadIdx.x >> 7;
    float s = 0.f, q = 0.f;
    for (long long r = (long long)blockIdx.x * 2 + half; r < NROWS;
         r += (long long)gridDim.x * 2) {
        float v = X[r * COUT + col];
        s += v;
        q += v * v;
    }
    ssum[half][col] = s;
    ssq[half][col] = q;
    __syncthreads();
    if (half == 0) {
        g_part_sum[blockIdx.x][col] = ssum[0][col] + ssum[1][col];
        g_part_sq[blockIdx.x][col]  = ssq[0][col] + ssq[1][col];
    }
}

__global__ void finalize_kernel(const float* __restrict__ g,
                                const float* __restrict__ b, int slot) {
    const int col = threadIdx.x;  // 128 threads
    float s = 0.f, q = 0.f;
    for (int i = 0; i < STATS_BLOCKS; i++) {
        s += g_part_sum[i][col];
        q += g_part_sq[i][col];
    }
    float mean = s * (1.0f / NROWS);
    float var = q * (1.0f / NROWS) - mean * mean;
    float inv = g[col] * rsqrtf(var + EPSBN);
    g_inv[slot][col] = inv;
    g_shift[slot][col] = b[col] - mean * inv;
}

// ---------------- BN apply (in place, slot 0) --------------------------------
__global__ void bn_apply_kernel(float4* __restrict__ X) {
    long long i = (long long)blockIdx.x * blockDim.x + threadIdx.x;
    const long long total = (long long)NROWS * COUT / 4;
    if (i >= total) return;
    int c4 = (int)(i & (COUT / 4 - 1)) * 4;
    float4 v = X[i];
    v.x = v.x * g_inv[0][c4 + 0] + g_shift[0][c4 + 0];
    v.y = v.y * g_inv[0][c4 + 1] + g_shift[0][c4 + 1];
    v.z = v.z * g_inv[0][c4 + 2] + g_shift[0][c4 + 2];
    v.w = v.w * g_inv[0][c4 + 3] + g_shift[0][c4 + 3];
    X[i] = v;
}

// ---------------- final: relu(bn(res) + bn(skip)) ----------------------------
__global__ void final_kernel(float4* __restrict__ out) {
    long long i = (long long)blockIdx.x * blockDim.x + threadIdx.x;
    const long long total = (long long)NROWS * COUT / 4;
    if (i >= total) return;
    int c4 = (int)(i & (COUT / 4 - 1)) * 4;
    const float4 r = ((const float4*)g_respre)[i];
    const float4 s = ((const float4*)g_skippre)[i];
    float4 o;
    o.x = fmaxf(r.x * g_inv[1][c4 + 0] + g_shift[1][c4 + 0] +
                s.x * g_inv[2][c4 + 0] + g_shift[2][c4 + 0], 0.f);
    o.y = fmaxf(r.y * g_inv[1][c4 + 1] + g_shift[1][c4 + 1] +
                s.y * g_inv[2][c4 + 1] + g_shift[2][c4 + 1], 0.f);
    o.z = fmaxf(r.z * g_inv[1][c4 + 2] + g_shift[1][c4 + 2] +
                s.z * g_inv[2][c4 + 2] + g_shift[2][c4 + 2], 0.f);
    o.w = fmaxf(r.w * g_inv[1][c4 + 3] + g_shift[1][c4 + 3] +
                s.w * g_inv[2][c4 + 3] + g_shift[2][c4 + 3], 0.f);
    out[i] = o;
}

// ---------------- launch ------------------------------------------------------
extern "C" void kernel_launch(void* const* d_in, const int* in_sizes, int n_in,
                              void* d_out, int out_size) {
    const float* feats = (const float*)d_in[0];
    const int*   nbr   = (const int*)d_in[1];
    const float* W1    = (const float*)d_in[2];
    const float* g1    = (const float*)d_in[3];
    const float* b1    = (const float*)d_in[4];
    const float* W2    = (const float*)d_in[5];
    const float* g2    = (const float*)d_in[6];
    const float* b2    = (const float*)d_in[7];
    const float* Wsk   = (const float*)d_in[8];
    const float* gsk   = (const float*)d_in[9];
    const float* bsk   = (const float*)d_in[10];
    float* out = (float*)d_out;

    float *hpre, *respre, *skippre;
    cudaGetSymbolAddress((void**)&hpre, g_hpre);
    cudaGetSymbolAddress((void**)&respre, g_respre);
    cudaGetSymbolAddress((void**)&skippre, g_skippre);

    const int grid = (NROWS + 127) / 128;  // 1563
    const long long total4 = (long long)NROWS * COUT / 4;
    const int egrid = (int)((total4 + 255) / 256);

    // skip branch pre-BN: feats @ Wsk
    conv_kernel<CIN1, false><<<grid, 256>>>(feats, nullptr, Wsk, skippre, 1);
    // conv1 pre-BN
    conv_kernel<CIN1, true><<<grid, 256>>>(feats, nbr, W1, hpre, NTAPS);
    // BN1 stats + apply in place
    stats_kernel<<<STATS_BLOCKS, 256>>>(hpre);
    finalize_kernel<<<1, COUT>>>(g1, b1, 0);
    bn_apply_kernel<<<egrid, 256>>>((float4*)hpre);
    // conv2 pre-BN
    conv_kernel<COUT, true><<<grid, 256>>>(hpre, nbr, W2, respre, NTAPS);
    // BN2 + BNskip stats
    stats_kernel<<<STATS_BLOCKS, 256>>>(respre);
    finalize_kernel<<<1, COUT>>>(g2, b2, 1);
    stats_kernel<<<STATS_BLOCKS, 256>>>(skippre);
    finalize_kernel<<<1, COUT>>>(gsk, bsk, 2);
    // out = relu(bn(res) + bn(skip))
    final_kernel<<<egrid, 256>>>((float4*)out);
}

// round 4
// speedup vs baseline: 2.2602x; 2.2486x over previous
#include <cuda_runtime.h>
#include <cuda_bf16.h>
#include <cstdint>

#define NROWS 200000
#define CIN1  64
#define COUT  128
#define NTAPS 27
#define EPSBN 1e-5f
#define STATS_BLOCKS 256

// ---------------- scratch (device globals; no allocation allowed) ----------
__device__ float g_hpre[(size_t)NROWS * COUT];    // conv1 pre-BN
__device__ float g_respre[(size_t)NROWS * COUT];  // conv2 pre-BN
__device__ float g_skippre[(size_t)NROWS * COUT]; // skip pre-BN
__device__ __nv_bfloat16 g_fhi[(size_t)NROWS * CIN1];
__device__ __nv_bfloat16 g_flo[(size_t)NROWS * CIN1];
__device__ __nv_bfloat16 g_hhi[(size_t)NROWS * COUT];
__device__ __nv_bfloat16 g_hlo[(size_t)NROWS * COUT];
__device__ __nv_bfloat16 g_w1hi[(size_t)NTAPS * COUT * CIN1];  // [tap][n][k] K-major
__device__ __nv_bfloat16 g_w1lo[(size_t)NTAPS * COUT * CIN1];
__device__ __nv_bfloat16 g_w2hi[(size_t)NTAPS * COUT * COUT];
__device__ __nv_bfloat16 g_w2lo[(size_t)NTAPS * COUT * COUT];
__device__ __nv_bfloat16 g_wskhi[(size_t)COUT * CIN1];
__device__ __nv_bfloat16 g_wsklo[(size_t)COUT * CIN1];
__device__ float g_part_sum[STATS_BLOCKS][COUT];
__device__ float g_part_sq[STATS_BLOCKS][COUT];
__device__ float g_inv[3][COUT];    // g * rsqrt(var+eps)
__device__ float g_shift[3][COUT];  // b - mean*inv

// ---------------- PTX helpers (baseline features only; no 'a'-gated ops) -----
__device__ __forceinline__ uint32_t smem_u32(const void* p) {
    uint32_t a;
    asm("{ .reg .u64 t; cvta.to.shared.u64 t, %1; cvt.u32.u64 %0, t; }"
        : "=r"(a) : "l"(p));
    return a;
}
__device__ __forceinline__ void cpasync16(uint32_t dst, const void* src, int srcsize) {
    asm volatile("cp.async.cg.shared.global [%0], [%1], 16, %2;"
                 :: "r"(dst), "l"(src), "r"(srcsize));
}
__device__ __forceinline__ void cpcommit() {
    asm volatile("cp.async.commit_group;");
}
__device__ __forceinline__ void ldm4(uint32_t* r, uint32_t addr) {
    asm volatile("ldmatrix.sync.aligned.m8n8.x4.shared.b16 {%0,%1,%2,%3}, [%4];"
                 : "=r"(r[0]), "=r"(r[1]), "=r"(r[2]), "=r"(r[3]) : "r"(addr));
}
__device__ __forceinline__ void mma16816(float* d, const uint32_t* a, const uint32_t* b) {
    asm volatile(
        "mma.sync.aligned.m16n8k16.row.col.f32.bf16.bf16.f32 "
        "{%0,%1,%2,%3},{%4,%5,%6,%7},{%8,%9},{%0,%1,%2,%3};"
        : "+f"(d[0]), "+f"(d[1]), "+f"(d[2]), "+f"(d[3])
        : "r"(a[0]), "r"(a[1]), "r"(a[2]), "r"(a[3]), "r"(b[0]), "r"(b[1]));
}

// smem tile geometry: bf16 rows padded to 40 elems (80B) -> ldmatrix conflict-free
#define ROWB   80
#define TILE_B (128 * ROWB)          // 10240 B per 128x32 tile
#define STAGE_B (4 * TILE_B)         // XH, XL, WH, WL
#define XH_OFF 0
#define XL_OFF TILE_B
#define WH_OFF (2 * TILE_B)
#define WL_OFF (3 * TILE_B)

// ---------------- HMMA gathered multi-tap GEMM -------------------------------
// Y[128-tile, 128] = sum_s gather(X)[128,32] @ W[32,128], split-bf16 3 terms.
template <bool GATHER>
__global__ __launch_bounds__(256, 2)
void mma_conv_kernel(const __nv_bfloat16* __restrict__ Xhi,
                     const __nv_bfloat16* __restrict__ Xlo,
                     const int* __restrict__ nbr,
                     const __nv_bfloat16* __restrict__ Whi,
                     const __nv_bfloat16* __restrict__ Wlo,
                     float* __restrict__ Y, int ntaps, int xk) {
    extern __shared__ char smem[];
    const uint32_t sb = smem_u32(smem);
    const int tid = threadIdx.x;
    const int wid = tid >> 5;
    const int lid = tid & 31;
    const int row0 = blockIdx.x * 128;
    const int cpt = xk >> 5;            // 32-wide k-chunks per tap
    const int nsub = ntaps * cpt;

    const int wm = (wid & 1) * 64;      // warp M offset in tile
    const int wn = (wid >> 1) * 32;     // warp N offset in tile

    // ---- per-thread load mapping: row r, two 16B chunks
    const int lr = tid >> 1;            // 0..127
    const int lc = (tid & 1) * 2;       // chunk pair 0/2

    float acc[4][4][4];
#pragma unroll
    for (int i = 0; i < 4; i++)
#pragma unroll
        for (int j = 0; j < 4; j++)
#pragma unroll
            for (int q = 0; q < 4; q++) acc[i][j][q] = 0.f;

    auto load_stage = [&](int s) {
        const int buf = s & 1;
        const int tap = s / cpt;
        const int kc = s - tap * cpt;
        const uint32_t st = sb + buf * STAGE_B;
        // X gathered rows
        const int grow = row0 + lr;
        int src;
        if (GATHER)
            src = (grow < NROWS) ? __ldg(nbr + (size_t)tap * NROWS + grow) : NROWS;
        else
            src = grow;
        const bool val = (unsigned)src < (unsigned)NROWS;
        const int srow = val ? src : 0;
        const int sz = val ? 16 : 0;
        const __nv_bfloat16* xh = Xhi + (size_t)srow * xk + kc * 32;
        const __nv_bfloat16* xl = Xlo + (size_t)srow * xk + kc * 32;
        const uint32_t xd = st + lr * ROWB + lc * 16;
#pragma unroll
        for (int c = 0; c < 2; c++) {
            cpasync16(xd + XH_OFF + c * 16, xh + (lc + c) * 8, sz);
            cpasync16(xd + XL_OFF + c * 16, xl + (lc + c) * 8, sz);
        }
        // W rows: n = lr (always valid)
        const __nv_bfloat16* wh = Whi + ((size_t)tap * 128 + lr) * xk + kc * 32;
        const __nv_bfloat16* wl = Wlo + ((size_t)tap * 128 + lr) * xk + kc * 32;
#pragma unroll
        for (int c = 0; c < 2; c++) {
            cpasync16(xd + WH_OFF + c * 16, wh + (lc + c) * 8, 16);
            cpasync16(xd + WL_OFF + c * 16, wl + (lc + c) * 8, 16);
        }
    };

    load_stage(0);
    cpcommit();

    // fragment address components
    const int b_nrow = (lid & 7) + ((lid >> 4) << 3);   // B ldmatrix row
    const int b_kof = ((lid >> 3) & 1) * 16;            // B k-byte offset within k16
    const int a_row = lid & 15;                         // A ldmatrix row
    const int a_kof = (lid >> 4) * 16;                  // A k-byte offset

    for (int s = 0; s < nsub; s++) {
        if (s + 1 < nsub) {
            load_stage(s + 1);
            cpcommit();
            asm volatile("cp.async.wait_group 1;");
        } else {
            asm volatile("cp.async.wait_group 0;");
        }
        __syncthreads();

        const uint32_t st = sb + (s & 1) * STAGE_B;
#pragma unroll
        for (int kh = 0; kh < 2; kh++) {
            const int kb = kh * 32;   // 16 bf16 = 32B
            uint32_t bh[4][2], bl[4][2];
#pragma unroll
            for (int half = 0; half < 2; half++) {
                const uint32_t wa =
                    st + WH_OFF + (wn + half * 16 + b_nrow) * ROWB + kb + b_kof;
                uint32_t r[4];
                ldm4(r, wa);
                bh[half * 2][0] = r[0]; bh[half * 2][1] = r[1];
                bh[half * 2 + 1][0] = r[2]; bh[half * 2 + 1][1] = r[3];
                ldm4(r, wa + (WL_OFF - WH_OFF));
                bl[half * 2][0] = r[0]; bl[half * 2][1] = r[1];
                bl[half * 2 + 1][0] = r[2]; bl[half * 2 + 1][1] = r[3];
            }
#pragma unroll
            for (int mi = 0; mi < 4; mi++) {
                uint32_t ah[4], al[4];
                const uint32_t aa =
                    st + XH_OFF + (wm + mi * 16 + a_row) * ROWB + kb + a_kof;
                ldm4(ah, aa);
                ldm4(al, aa + (XL_OFF - XH_OFF));
#pragma unroll
                for (int ni = 0; ni < 4; ni++) {
                    mma16816(acc[mi][ni], ah, bh[ni]);
                    mma16816(acc[mi][ni], ah, bl[ni]);
                    mma16816(acc[mi][ni], al, bh[ni]);
                }
            }
        }
        __syncthreads();
    }

    // ---- epilogue: write fp32
#pragma unroll
    for (int mi = 0; mi < 4; mi++) {
        const int m0 = row0 + wm + mi * 16 + (lid >> 2);
#pragma unroll
        for (int ni = 0; ni < 4; ni++) {
            const int col = wn + ni * 8 + 2 * (lid & 3);
            if (m0 < NROWS)
                *(float2*)(Y + (size_t)m0 * 128 + col) =
                    make_float2(acc[mi][ni][0], acc[mi][ni][1]);
            if (m0 + 8 < NROWS)
                *(float2*)(Y + (size_t)(m0 + 8) * 128 + col) =
                    make_float2(acc[mi][ni][2], acc[mi][ni][3]);
        }
    }
}

// ---------------- prep: W transpose + bf16 split -----------------------------
__global__ void wsplit_kernel(const float* __restrict__ W,
                              __nv_bfloat16* __restrict__ hi,
                              __nv_bfloat16* __restrict__ lo, int taps, int K) {
    int i = blockIdx.x * blockDim.x + threadIdx.x;
    int total = taps * 128 * K;
    if (i >= total) return;
    int kk = i % K;
    int t2 = i / K;
    int n = t2 & 127;
    int tap = t2 >> 7;
    float v = __ldg(W + ((size_t)tap * K + kk) * 128 + n);
    __nv_bfloat16 h = __float2bfloat16(v);
    hi[i] = h;
    lo[i] = __float2bfloat16(v - __bfloat162float(h));
}

// ---------------- prep: feats bf16 split (vector) ----------------------------
__global__ void xsplit_kernel(const float4* __restrict__ X,
                              uint2* __restrict__ hi, uint2* __restrict__ lo,
                              long long n4) {
    long long i = (long long)blockIdx.x * blockDim.x + threadIdx.x;
    if (i >= n4) return;
    float4 v = X[i];
    __nv_bfloat16 hx = __float2bfloat16(v.x), hy = __float2bfloat16(v.y);
    __nv_bfloat16 hz = __float2bfloat16(v.z), hw = __float2bfloat16(v.w);
    __nv_bfloat162 h01, h23, l01, l23;
    h01.x = hx; h01.y = hy; h23.x = hz; h23.y = hw;
    l01.x = __float2bfloat16(v.x - __bfloat162float(hx));
    l01.y = __float2bfloat16(v.y - __bfloat162float(hy));
    l23.x = __float2bfloat16(v.z - __bfloat162float(hz));
    l23.y = __float2bfloat16(v.w - __bfloat162float(hw));
    hi[i] = make_uint2(*(uint32_t*)&h01, *(uint32_t*)&h23);
    lo[i] = make_uint2(*(uint32_t*)&l01, *(uint32_t*)&l23);
}

// ---------------- deterministic column stats --------------------------------
__global__ void stats_kernel(const float* __restrict__ X) {
    __shared__ float ssum[2][COUT];
    __shared__ float ssq[2][COUT];
    const int col = threadIdx.x & (COUT - 1);
    const int half = threadIdx.x >> 7;
    float s = 0.f, q = 0.f;
    for (long long r = (long long)blockIdx.x * 2 + half; r < NROWS;
         r += (long long)gridDim.x * 2) {
        float v = X[r * COUT + col];
        s += v;
        q += v * v;
    }
    ssum[half][col] = s;
    ssq[half][col] = q;
    __syncthreads();
    if (half == 0) {
        g_part_sum[blockIdx.x][col] = ssum[0][col] + ssum[1][col];
        g_part_sq[blockIdx.x][col]  = ssq[0][col] + ssq[1][col];
    }
}

__global__ void finalize_kernel(const float* __restrict__ g,
                                const float* __restrict__ b, int slot) {
    const int col = threadIdx.x;  // 128 threads
    float s = 0.f, q = 0.f;
    for (int i = 0; i < STATS_BLOCKS; i++) {
        s += g_part_sum[i][col];
        q += g_part_sq[i][col];
    }
    float mean = s * (1.0f / NROWS);
    float var = q * (1.0f / NROWS) - mean * mean;
    float inv = g[col] * rsqrtf(var + EPSBN);
    g_inv[slot][col] = inv;
    g_shift[slot][col] = b[col] - mean * inv;
}

// ---------------- BN apply (slot 0) fused with bf16 split --------------------
__global__ void bnsplit_kernel(const float4* __restrict__ X,
                               uint2* __restrict__ hi, uint2* __restrict__ lo) {
    long long i = (long long)blockIdx.x * blockDim.x + threadIdx.x;
    const long long total = (long long)NROWS * COUT / 4;
    if (i >= total) return;
    int c4 = (int)(i & (COUT / 4 - 1)) * 4;
    float4 v = X[i];
    v.x = v.x * g_inv[0][c4 + 0] + g_shift[0][c4 + 0];
    v.y = v.y * g_inv[0][c4 + 1] + g_shift[0][c4 + 1];
    v.z = v.z * g_inv[0][c4 + 2] + g_shift[0][c4 + 2];
    v.w = v.w * g_inv[0][c4 + 3] + g_shift[0][c4 + 3];
    __nv_bfloat16 hx = __float2bfloat16(v.x), hy = __float2bfloat16(v.y);
    __nv_bfloat16 hz = __float2bfloat16(v.z), hw = __float2bfloat16(v.w);
    __nv_bfloat162 h01, h23, l01, l23;
    h01.x = hx; h01.y = hy; h23.x = hz; h23.y = hw;
    l01.x = __float2bfloat16(v.x - __bfloat162float(hx));
    l01.y = __float2bfloat16(v.y - __bfloat162float(hy));
    l23.x = __float2bfloat16(v.z - __bfloat162float(hz));
    l23.y = __float2bfloat16(v.w - __bfloat162float(hw));
    hi[i] = make_uint2(*(uint32_t*)&h01, *(uint32_t*)&h23);
    lo[i] = make_uint2(*(uint32_t*)&l01, *(uint32_t*)&l23);
}

// ---------------- final: relu(bn(res) + bn(skip)) ----------------------------
__global__ void final_kernel(float4* __restrict__ out) {
    long long i = (long long)blockIdx.x * blockDim.x + threadIdx.x;
    const long long total = (long long)NROWS * COUT / 4;
    if (i >= total) return;
    int c4 = (int)(i & (COUT / 4 - 1)) * 4;
    const float4 r = ((const float4*)g_respre)[i];
    const float4 s = ((const float4*)g_skippre)[i];
    float4 o;
    o.x = fmaxf(r.x * g_inv[1][c4 + 0] + g_shift[1][c4 + 0] +
                s.x * g_inv[2][c4 + 0] + g_shift[2][c4 + 0], 0.f);
    o.y = fmaxf(r.y * g_inv[1][c4 + 1] + g_shift[1][c4 + 1] +
                s.y * g_inv[2][c4 + 1] + g_shift[2][c4 + 1], 0.f);
    o.z = fmaxf(r.z * g_inv[1][c4 + 2] + g_shift[1][c4 + 2] +
                s.z * g_inv[2][c4 + 2] + g_shift[2][c4 + 2], 0.f);
    o.w = fmaxf(r.w * g_inv[1][c4 + 3] + g_shift[1][c4 + 3] +
                s.w * g_inv[2][c4 + 3] + g_shift[2][c4 + 3], 0.f);
    out[i] = o;
}

// ---------------- launch ------------------------------------------------------
extern "C" void kernel_launch(void* const* d_in, const int* in_sizes, int n_in,
                              void* d_out, int out_size) {
    const float* feats = (const float*)d_in[0];
    const int*   nbr   = (const int*)d_in[1];
    const float* W1    = (const float*)d_in[2];
    const float* g1    = (const float*)d_in[3];
    const float* b1    = (const float*)d_in[4];
    const float* W2    = (const float*)d_in[5];
    const float* g2    = (const float*)d_in[6];
    const float* b2    = (const float*)d_in[7];
    const float* Wsk   = (const float*)d_in[8];
    const float* gsk   = (const float*)d_in[9];
    const float* bsk   = (const float*)d_in[10];
    float* out = (float*)d_out;

    float *hpre, *respre, *skippre;
    __nv_bfloat16 *fhi, *flo, *hhi, *hlo, *w1hi, *w1lo, *w2hi, *w2lo, *wskhi, *wsklo;
    cudaGetSymbolAddress((void**)&hpre, g_hpre);
    cudaGetSymbolAddress((void**)&respre, g_respre);
    cudaGetSymbolAddress((void**)&skippre, g_skippre);
    cudaGetSymbolAddress((void**)&fhi, g_fhi);
    cudaGetSymbolAddress((void**)&flo, g_flo);
    cudaGetSymbolAddress((void**)&hhi, g_hhi);
    cudaGetSymbolAddress((void**)&hlo, g_hlo);
    cudaGetSymbolAddress((void**)&w1hi, g_w1hi);
    cudaGetSymbolAddress((void**)&w1lo, g_w1lo);
    cudaGetSymbolAddress((void**)&w2hi, g_w2hi);
    cudaGetSymbolAddress((void**)&w2lo, g_w2lo);
    cudaGetSymbolAddress((void**)&wskhi, g_wskhi);
    cudaGetSymbolAddress((void**)&wsklo, g_wsklo);

    const int SMEM_BYTES = 2 * STAGE_B;  // 81920
    cudaFuncSetAttribute(mma_conv_kernel<true>,
                         cudaFuncAttributeMaxDynamicSharedMemorySize, SMEM_BYTES);
    cudaFuncSetAttribute(mma_conv_kernel<false>,
                         cudaFuncAttributeMaxDynamicSharedMemorySize, SMEM_BYTES);

    const int grid = (NROWS + 127) / 128;  // 1563
    const long long total4 = (long long)NROWS * COUT / 4;
    const int egrid = (int)((total4 + 255) / 256);
    const long long f4 = (long long)NROWS * CIN1 / 4;

    // ---- prep: weight transpose+split, feats split
    wsplit_kernel<<<(NTAPS * 128 * CIN1 + 255) / 256, 256>>>(W1, w1hi, w1lo, NTAPS, CIN1);
    wsplit_kernel<<<(NTAPS * 128 * COUT + 255) / 256, 256>>>(W2, w2hi, w2lo, NTAPS, COUT);
    wsplit_kernel<<<(128 * CIN1 + 255) / 256, 256>>>(Wsk, wskhi, wsklo, 1, CIN1);
    xsplit_kernel<<<(int)((f4 + 255) / 256), 256>>>((const float4*)feats,
                                                    (uint2*)fhi, (uint2*)flo, f4);

    // ---- skip: feats @ Wsk (no gather)
    mma_conv_kernel<false><<<grid, 256, SMEM_BYTES>>>(fhi, flo, nullptr,
                                                      wskhi, wsklo, skippre, 1, CIN1);
    // ---- conv1: 27 taps, K=64
    mma_conv_kernel<true><<<grid, 256, SMEM_BYTES>>>(fhi, flo, nbr,
                                                     w1hi, w1lo, hpre, NTAPS, CIN1);
    // ---- BN1 stats + fused apply+split
    stats_kernel<<<STATS_BLOCKS, 256>>>(hpre);
    finalize_kernel<<<1, COUT>>>(g1, b1, 0);
    bnsplit_kernel<<<egrid, 256>>>((const float4*)hpre, (uint2*)hhi, (uint2*)hlo);
    // ---- conv2: 27 taps, K=128
    mma_conv_kernel<true><<<grid, 256, SMEM_BYTES>>>(hhi, hlo, nbr,
                                                     w2hi, w2lo, respre, NTAPS, COUT);
    // ---- BN2 + BNskip stats
    stats_kernel<<<STATS_BLOCKS, 256>>>(respre);
    finalize_kernel<<<1, COUT>>>(g2, b2, 1);
    stats_kernel<<<STATS_BLOCKS, 256>>>(skippre);
    finalize_kernel<<<1, COUT>>>(gsk, bsk, 2);
    // ---- out = relu(bn(res) + bn(skip))
    final_kernel<<<egrid, 256>>>((float4*)out);
}